// round 2
// baseline (speedup 1.0000x reference)
#include <cuda_runtime.h>
#include <cstdint>

// Problem shape (fixed by the dataset)
#define BB 4
#define NN 4096
#define DD 4096
#define EE 64
#define BN (BB * NN)

// ---- scratch (no allocations allowed) ----
__device__ float          g_probsT[BB][EE][NN];   // 4 MB: probs transposed [b][e][n]
__device__ unsigned short g_sorted[BB][EE][NN];   // 2 MB: per (b,e) token order, descending prob

// ============================================================================
// Kernel 1: router GEMM (fp32 via packed fma.rn.f32x2) + fused softmax.
// grid 128 CTAs x 256 threads; each CTA: 128 tokens x all 64 experts, K=4096.
// Two-level accumulation (per-32k tile accumulator folded into main) keeps
// fp32 rounding noise ~8e-7 so the greedy ranking matches the reference.
// ============================================================================
__global__ void __launch_bounds__(256) k_router_gemm(const float* __restrict__ x,
                                                     const float* __restrict__ W)
{
    // union: phase A (xs 32x130 + ws 32x66 = 6272 floats), phase B (ls 128x65 = 8320)
    __shared__ __align__(16) float su[8320];
    float (*xs)[130] = reinterpret_cast<float (*)[130]>(su);          // [k][tok], stride even -> 8B-aligned pairs
    float (*ws)[66]  = reinterpret_cast<float (*)[66]>(su + 4160);    // [k][e]
    float (*ls)[65]  = reinterpret_cast<float (*)[65]>(su);           // logits/probs [tok][e]
    __shared__ float sinv[128];

    const int tid = threadIdx.x;
    const int tt  = tid & 15;   // token-pair group: pairs at tokens 2*tt + 32*i
    const int te  = tid >> 4;   // expert group: experts te*4 .. te*4+3
    const int m0  = blockIdx.x * 128;

    unsigned long long accm[4][4] = {};  // [token-pair i][expert j], f32x2 packed

    for (int kt = 0; kt < DD / 32; ++kt) {
        __syncthreads();
        // load x tile: 128 tok x 32 k (float4 along k, transposed scalar stores)
        #pragma unroll
        for (int it = 0; it < 4; ++it) {
            int f = tid + it * 256;
            int r = f >> 3, c4 = f & 7;
            float4 v = __ldcs(reinterpret_cast<const float4*>(
                x + (size_t)(m0 + r) * DD + kt * 32 + c4 * 4));
            xs[c4 * 4 + 0][r] = v.x; xs[c4 * 4 + 1][r] = v.y;
            xs[c4 * 4 + 2][r] = v.z; xs[c4 * 4 + 3][r] = v.w;
        }
        // load W tile: 64 e x 32 k
        #pragma unroll
        for (int it = 0; it < 2; ++it) {
            int f = tid + it * 256;
            int e = f >> 3, c4 = f & 7;
            float4 v = __ldg(reinterpret_cast<const float4*>(
                W + (size_t)e * DD + kt * 32 + c4 * 4));
            ws[c4 * 4 + 0][e] = v.x; ws[c4 * 4 + 1][e] = v.y;
            ws[c4 * 4 + 2][e] = v.z; ws[c4 * 4 + 3][e] = v.w;
        }
        __syncthreads();

        unsigned long long acct[4][4] = {};  // fresh tile accumulator
        #pragma unroll 4
        for (int k = 0; k < 32; ++k) {
            unsigned long long wd[4];
            #pragma unroll
            for (int j = 0; j < 4; ++j) {
                unsigned wu = __float_as_uint(ws[k][te * 4 + j]);
                asm("mov.b64 %0, {%1, %1};" : "=l"(wd[j]) : "r"(wu));
            }
            #pragma unroll
            for (int i = 0; i < 4; ++i) {
                // token pair (2*tt + 32*i, 2*tt + 32*i + 1): one LDS.64
                unsigned long long xp =
                    *reinterpret_cast<const unsigned long long*>(&xs[k][2 * tt + 32 * i]);
                #pragma unroll
                for (int j = 0; j < 4; ++j)
                    asm("fma.rn.f32x2 %0, %1, %2, %0;"
                        : "+l"(acct[i][j]) : "l"(xp), "l"(wd[j]));
            }
        }
        #pragma unroll
        for (int i = 0; i < 4; ++i)
            #pragma unroll
            for (int j = 0; j < 4; ++j)
                asm("add.rn.f32x2 %0, %0, %1;" : "+l"(accm[i][j]) : "l"(acct[i][j]));
    }
    __syncthreads();

    // spill logits to smem [tok][e]; acc lo-half = even token, hi-half = odd token
    #pragma unroll
    for (int i = 0; i < 4; ++i)
        #pragma unroll
        for (int j = 0; j < 4; ++j) {
            int tok = 2 * tt + 32 * i, e = te * 4 + j;
            ls[tok + 0][e] = __uint_as_float((unsigned)(accm[i][j] & 0xffffffffu));
            ls[tok + 1][e] = __uint_as_float((unsigned)(accm[i][j] >> 32));
        }
    __syncthreads();

    // softmax: one thread per token (threads 0..127)
    if (tid < 128) {
        const int t = tid;
        float m = -1e30f;
        #pragma unroll
        for (int e = 0; e < EE; ++e) m = fmaxf(m, ls[t][e]);
        float s = 0.f;
        #pragma unroll
        for (int e = 0; e < EE; ++e) { float v = expf(ls[t][e] - m); ls[t][e] = v; s += v; }
        sinv[t] = 1.0f / s;
    }
    __syncthreads();

    // transposed coalesced write: probsT[b][e][n0+tok]
    const int b = m0 >> 12, n0 = m0 & (NN - 1);
    #pragma unroll
    for (int it = 0; it < 32; ++it) {
        int f = tid + it * 256;
        int e = f >> 7, tok = f & 127;
        g_probsT[b][e][n0 + tok] = ls[tok][e] * sinv[tok];
    }
}

// ============================================================================
// Kernel 2: per (batch, expert) descending bitonic sort of 4096 tokens by prob.
// key = prob_bits<<32 | (4095 - tok): probs > 0 -> uint-monotone; tie-break
// favors the lower token index, matching jax.lax.top_k.
// ============================================================================
__global__ void __launch_bounds__(512) k_sort()
{
    __shared__ unsigned long long sk[NN];  // 32 KB
    const int b = blockIdx.x >> 6;
    const int e = blockIdx.x & 63;
    const int tid = threadIdx.x;
    const float* __restrict__ col = g_probsT[b][e];

    for (int r = tid; r < NN; r += 512) {
        unsigned pb = __float_as_uint(col[r]);
        sk[r] = ((unsigned long long)pb << 32) | (unsigned)(NN - 1 - r);
    }
    __syncthreads();

    for (int k2 = 2; k2 <= NN; k2 <<= 1) {
        for (int j = k2 >> 1; j > 0; j >>= 1) {
            #pragma unroll
            for (int it = 0; it < NN / 512; ++it) {
                int i = tid + it * 512;
                int ixj = i ^ j;
                if (ixj > i) {
                    bool asc = (i & k2) != 0;
                    unsigned long long a = sk[i], c = sk[ixj];
                    bool sw = asc ? (a > c) : (a < c);
                    if (sw) { sk[i] = c; sk[ixj] = a; }
                }
            }
            __syncthreads();
        }
    }
    for (int r = tid; r < NN; r += 512)
        g_sorted[b][e][r] = (unsigned short)(NN - 1u - (unsigned)(sk[r] & 0xffffffffu));
}

// ============================================================================
// Kernel 3: greedy expert-preferred assignment + output.
// One CTA per batch; experts j = E-1..0 take their top-kj unmasked tokens
// (block ballot + prefix walk over the presorted list). Next expert's first
// chunk is prefetched to hide the per-expert load latency.
// Output: [ M as float32 (B*N) | M_probs float32 (B*N) ]
// ============================================================================
__global__ void __launch_bounds__(512) k_greedy(const float* __restrict__ c,
                                                float* __restrict__ out)
{
    const int b = blockIdx.x;
    const int tid = threadIdx.x;
    __shared__ unsigned      maskw[NN / 32];  // chosen-token bitset
    __shared__ unsigned char sM[NN];
    __shared__ int   wsum[16];
    __shared__ float sc[EE];

    for (int i = tid; i < NN / 32; i += 512) maskw[i] = 0u;
    for (int i = tid; i < NN; i += 512) sM[i] = 0;
    if (tid < EE) sc[tid] = c[tid];
    __syncthreads();

    const int lane = tid & 31, wrp = tid >> 5;
    int tok = (int)g_sorted[b][EE - 1][tid];  // prefetch first expert's chunk 0

    for (int j = EE - 1; j >= 0; --j) {
        int pre = (j > 0) ? (int)g_sorted[b][j - 1][tid] : 0;  // prefetch next expert
        int kj = (int)floorf(sc[j] * (float)NN);
        if (kj > NN) kj = NN;
        int need = kj;
        int pos = 0;
        int cur = tok;
        while (need > 0 && pos < NN) {
            if (pos > 0) {
                int idx = pos + tid;
                cur = (idx < NN) ? (int)g_sorted[b][j][idx] : 0;
            }
            int valid = 0;
            if (pos + tid < NN)
                valid = ((maskw[cur >> 5] >> (cur & 31)) & 1u) ^ 1u;
            unsigned bal = __ballot_sync(0xffffffffu, valid);
            int lp = __popc(bal & ((1u << lane) - 1u));
            if (lane == 0) wsum[wrp] = __popc(bal);
            __syncthreads();
            int base = 0, total = 0;
            #pragma unroll
            for (int w = 0; w < 16; ++w) { int s = wsum[w]; if (w < wrp) base += s; total += s; }
            if (valid && (base + lp) < need) {
                sM[cur] = (unsigned char)j;
                atomicOr(&maskw[cur >> 5], 1u << (cur & 31));
            }
            need -= (total < need ? total : need);
            pos += 512;
            __syncthreads();
        }
        tok = pre;
    }

    // outputs: M (as float), then M_probs
    for (int t = tid; t < NN; t += 512) {
        int j = sM[t];
        out[(size_t)b * NN + t] = (float)j;
        out[(size_t)BN + (size_t)b * NN + t] = g_probsT[b][j][t];
    }
}

// ============================================================================
extern "C" void kernel_launch(void* const* d_in, const int* in_sizes, int n_in,
                              void* d_out, int out_size)
{
    const float* x = (const float*)d_in[0];   // [B, N, D]
    const float* W = (const float*)d_in[1];   // [E, D]
    const float* c = (const float*)d_in[2];   // [E]
    float* out = (float*)d_out;

    k_router_gemm<<<BN / 128, 256>>>(x, W);
    k_sort<<<BB * EE, 512>>>();
    k_greedy<<<BB, 512>>>(c, out);
}